// round 5
// baseline (speedup 1.0000x reference)
#include <cuda_runtime.h>

#define FULL 0xffffffffu
#define L2E 1.4426950408889634f

typedef unsigned long long u64;

// shared layout offsets (floats), all lane-fastest (conflict-free)
#define L0W 0
#define L0B 256
#define L1Wa 512
#define L1Wb 640
#define L1B 768
#define L2Wa 896
#define L2Wb 960
#define L2B 1024
#define L3Wa 1088
#define L3Wb 1120
#define L3B 1152
#define L4W 1184
#define L4B 1216
#define L5W 1232
#define L5B 1248
#define L6W 1256
#define L6B 1264
#define L7W 1268
#define L7B 1272
#define L8W 1274
#define L8B 1276
#define SC  1280
#define SM_TOT 1288

struct TreeParams {
    const float* w[9];
    const float* b[9];
    const float* alpha;
    const float* beta;
    const float* gamma;
    const float* root_w;
    const float* root_b;
};

__device__ __forceinline__ float ex2f(float x) {
    float y; asm("ex2.approx.ftz.f32 %0, %1;" : "=f"(y) : "f"(x)); return y;
}
__device__ __forceinline__ float rcpf(float x) {
    float y; asm("rcp.approx.ftz.f32 %0, %1;" : "=f"(y) : "f"(x)); return y;
}

// ---- f32x2 packed helpers (sm_100+): 2 fp32 ops per instruction ----
__device__ __forceinline__ u64 pk(float lo, float hi) {
    u64 r; asm("mov.b64 %0, {%1, %2};" : "=l"(r) : "f"(lo), "f"(hi)); return r;
}
__device__ __forceinline__ void upk(u64 v, float& lo, float& hi) {
    asm("mov.b64 {%0, %1}, %2;" : "=f"(lo), "=f"(hi) : "l"(v));
}
__device__ __forceinline__ u64 fma2(u64 a, u64 b, u64 c) {
    u64 d; asm("fma.rn.f32x2 %0, %1, %2, %3;" : "=l"(d) : "l"(a), "l"(b), "l"(c)); return d;
}
__device__ __forceinline__ u64 add2(u64 a, u64 b) {
    u64 d; asm("add.rn.f32x2 %0, %1, %2;" : "=l"(d) : "l"(a), "l"(b)); return d;
}
__device__ __forceinline__ u64 mul2(u64 a, u64 b) {
    u64 d; asm("mul.rn.f32x2 %0, %1, %2;" : "=l"(d) : "l"(a), "l"(b)); return d;
}
__device__ __forceinline__ u64 bc2(float v) {  // broadcast scalar to both halves
    u64 r; asm("mov.b64 %0, {%1, %1};" : "=l"(r) : "f"(v)); return r;
}

struct NckC {          // packed nck coefficients (alpha/beta/gamma folded)
    u64 cA2, dA2, cB2, dB2, cG2;
};

// scalar nck: single reciprocal over common denominator (1+e1)(1+e2)(0.436+e3)
__device__ __forceinline__ float nck_eval(float z, float cA, float dA,
                                          float cB, float dB, float cG) {
    const float e1 = ex2f(fmaf(-L2E / 8.98f, z, 6.39f * L2E));
    const float e2 = ex2f(fmaf(-L2E / 4.25f, z, -4.4f * L2E));
    const float e3 = ex2f(fmaf(-0.132f * L2E, z, 0.132f * 16.74f * L2E));
    const float a1 = 1.0f + e1;
    const float a2 = 1.0f + e2;
    const float a3 = 0.436f + e3;
    const float d12 = a1 * a2;
    const float R = rcpf(d12 * a3);
    const float n1 = fmaf(cA, z, dA);
    const float n2 = fmaf(cB, z, dB);
    const float q = fmaf(n1, a2, n2 * a1);
    const float num = fmaf(q, a3, cG * d12);
    return num * R;
}

// packed nck: 2 independent evaluations per call; all FMA-pipe work in f32x2,
// only ex2/rcp unpacked to scalar MUFU ops.
__device__ __forceinline__ u64 nck2p(u64 zz, const NckC& C) {
    const u64 K1 = bc2(-L2E / 8.98f),  C1 = bc2(6.39f * L2E);
    const u64 K2 = bc2(-L2E / 4.25f),  C2 = bc2(-4.4f * L2E);
    const u64 K3 = bc2(-0.132f * L2E), C3 = bc2(0.132f * 16.74f * L2E);
    const u64 ONE2 = bc2(1.0f), P436 = bc2(0.436f);

    const u64 t1 = fma2(K1, zz, C1);
    const u64 t2 = fma2(K2, zz, C2);
    const u64 t3 = fma2(K3, zz, C3);
    float x1a, x1b, x2a, x2b, x3a, x3b;
    upk(t1, x1a, x1b); upk(t2, x2a, x2b); upk(t3, x3a, x3b);
    const u64 e1 = pk(ex2f(x1a), ex2f(x1b));
    const u64 e2 = pk(ex2f(x2a), ex2f(x2b));
    const u64 e3 = pk(ex2f(x3a), ex2f(x3b));
    const u64 a1 = add2(e1, ONE2);
    const u64 a2 = add2(e2, ONE2);
    const u64 a3 = add2(e3, P436);
    const u64 d12 = mul2(a1, a2);
    const u64 den = mul2(d12, a3);
    float dla, dlb;
    upk(den, dla, dlb);
    const u64 R = pk(rcpf(dla), rcpf(dlb));
    const u64 n1 = fma2(C.cA2, zz, C.dA2);
    const u64 n2 = fma2(C.cB2, zz, C.dB2);
    const u64 q = fma2(n1, a2, mul2(n2, a1));
    const u64 num = fma2(q, a3, mul2(C.cG2, d12));
    return mul2(num, R);
}

__global__ __launch_bounds__(256) void asym_tree_kernel(
    const float* __restrict__ x, TreeParams P, float* __restrict__ out, int B) {
    __shared__ float sm[SM_TOT];

    const int tid = threadIdx.x;
    const int lane = tid & 31;

    // ---- stage params, lane-fastest transposed layouts ----
    {
        const int t = tid >> 5, l = tid & 31;
        const int r = l * 8 + t;
        sm[L0W + tid] = P.w[0][255 - r];
        sm[L0B + tid] = P.b[0][510 - r];
    }
    if (tid < 128) {
        const int s = tid >> 5, l = tid & 31;
        const int k = l * 4 + s;
        sm[L1Wa + tid] = P.w[1][2 * k];
        sm[L1Wb + tid] = P.w[1][2 * k + 1];
        sm[L1B + tid]  = P.b[1][127 + k];
    }
    if (tid < 64) {
        const int s = tid >> 5, l = tid & 31;
        const int k = l * 2 + s;
        sm[L2Wa + tid] = P.w[2][2 * k];
        sm[L2Wb + tid] = P.w[2][2 * k + 1];
        sm[L2B + tid]  = P.b[2][63 + k];
    }
    if (tid < 32) {
        sm[L3Wa + tid] = P.w[3][2 * tid];
        sm[L3Wb + tid] = P.w[3][2 * tid + 1];
        sm[L3B + tid]  = P.b[3][31 + tid];
        sm[L4W + tid]  = P.w[4][tid];
    }
    if (tid < 16) {
        sm[L4B + tid] = P.b[4][15 + tid];
        sm[L5W + tid] = P.w[5][tid];
    }
    if (tid < 8) {
        sm[L5B + tid] = P.b[5][7 + tid];
        sm[L6W + tid] = P.w[6][tid];
    }
    if (tid < 4) {
        sm[L6B + tid] = P.b[6][3 + tid];
        sm[L7W + tid] = P.w[7][tid];
    }
    if (tid < 2) {
        sm[L7B + tid] = P.b[7][1 + tid];
        sm[L8W + tid] = P.w[8][tid];
    }
    if (tid == 0) {
        sm[L8B] = P.b[8][0];
        sm[SC + 0] = P.alpha[0];  sm[SC + 1] = P.beta[0]; sm[SC + 2] = P.gamma[0];
        sm[SC + 3] = P.root_w[0]; sm[SC + 4] = P.root_b[0];
    }
    __syncthreads();

    const float A = sm[SC], Bt = sm[SC + 1], G = sm[SC + 2];
    const float cA = A * 0.0878f, dA = -A * 0.0878f * 113.68f;
    const float cB = Bt * 0.129f, dB = -Bt * 0.129f * 69.62f;
    const float cG = G * 2.23f;
    NckC C;
    C.cA2 = bc2(cA); C.dA2 = bc2(dA);
    C.cB2 = bc2(cB); C.dB2 = bc2(dB);
    C.cG2 = bc2(cG);

    const int warp = (blockIdx.x * 256 + tid) >> 5;
    const int e0 = warp * 4;
    if (e0 >= B) return;

    // ---- levels 0-3, two elements packed per f32x2 stream, two pairs ----
    float c[4];
#pragma unroll
    for (int p = 0; p < 2; ++p) {
        const int eA = e0 + 2 * p;
        const int eB = eA + 1;
        const float* xeA = x + (size_t)(eA < B ? eA : B - 1) * 256;
        const float* xeB = x + (size_t)(eB < B ? eB : B - 1) * 256;
        const float4 a4A = reinterpret_cast<const float4*>(xeA)[lane * 2];
        const float4 b4A = reinterpret_cast<const float4*>(xeA)[lane * 2 + 1];
        const float4 a4B = reinterpret_cast<const float4*>(xeB)[lane * 2];
        const float4 b4B = reinterpret_cast<const float4*>(xeB)[lane * 2 + 1];
        const float xvA[8] = {a4A.x, a4A.y, a4A.z, a4A.w, b4A.x, b4A.y, b4A.z, b4A.w};
        const float xvB[8] = {a4B.x, a4B.y, a4B.z, a4B.w, b4B.x, b4B.y, b4B.z, b4B.w};

        // levels 0+1 fused, packed
        u64 t1[4];
#pragma unroll
        for (int s = 0; s < 4; ++s) {
            const float w0a = sm[L0W + (2 * s) * 32 + lane];
            const float b0a = sm[L0B + (2 * s) * 32 + lane];
            const float w0b = sm[L0W + (2 * s + 1) * 32 + lane];
            const float b0b = sm[L0B + (2 * s + 1) * 32 + lane];
            const u64 z0 = fma2(bc2(w0a), pk(xvA[2 * s], xvB[2 * s]), bc2(b0a));
            const u64 z1 = fma2(bc2(w0b), pk(xvA[2 * s + 1], xvB[2 * s + 1]), bc2(b0b));
            const u64 u0 = nck2p(z0, C);
            const u64 u1 = nck2p(z1, C);
            const u64 zl1 = fma2(bc2(sm[L1Wa + s * 32 + lane]), u0,
                           fma2(bc2(sm[L1Wb + s * 32 + lane]), u1,
                                bc2(sm[L1B + s * 32 + lane])));
            t1[s] = nck2p(zl1, C);
        }

        // reversal: unpack, shfl.xor(31) each half, repack (slot flip)
        u64 u[4];
#pragma unroll
        for (int s = 0; s < 4; ++s) {
            float lo, hi;
            upk(t1[3 - s], lo, hi);
            u[s] = pk(__shfl_xor_sync(FULL, lo, 31), __shfl_xor_sync(FULL, hi, 31));
        }

        // level 2: N=64, 2 outputs/lane, packed
        u64 t2[2];
#pragma unroll
        for (int s = 0; s < 2; ++s) {
            const u64 z = fma2(bc2(sm[L2Wa + s * 32 + lane]), u[2 * s],
                         fma2(bc2(sm[L2Wb + s * 32 + lane]), u[2 * s + 1],
                              bc2(sm[L2B + s * 32 + lane])));
            t2[s] = nck2p(z, C);
        }
        float lo1, hi1, lo0, hi0;
        upk(t2[1], lo1, hi1);
        upk(t2[0], lo0, hi0);
        const u64 r0 = pk(__shfl_xor_sync(FULL, lo1, 31), __shfl_xor_sync(FULL, hi1, 31));
        const u64 r1 = pk(__shfl_xor_sync(FULL, lo0, 31), __shfl_xor_sync(FULL, hi0, 31));

        // level 3: N=32, 1 output/lane, packed -> natural order
        const u64 z3 = fma2(bc2(sm[L3Wa + lane]), r0,
                      fma2(bc2(sm[L3Wb + lane]), r1, bc2(sm[L3B + lane])));
        const u64 cc = nck2p(z3, C);
        upk(cc, c[2 * p], c[2 * p + 1]);
    }

    // ---- level 4: N=16, 2 elements per warp-nck (scalar tail) ----
    const bool hi = lane >= 16;
    const int k4 = lane & 15;
    const int i4a = 31 - 2 * k4;
    const int i4b = 30 - 2 * k4;
    const float w4a = sm[L4W + 2 * k4], w4b = sm[L4W + 2 * k4 + 1];
    const float bb4 = sm[L4B + k4];

    float v4p0, v4p1;
    {
        const float a0 = __shfl_sync(FULL, c[0], i4a);
        const float a1 = __shfl_sync(FULL, c[1], i4a);
        const float b0 = __shfl_sync(FULL, c[0], i4b);
        const float b1 = __shfl_sync(FULL, c[1], i4b);
        const float pa = hi ? a1 : a0;
        const float pb = hi ? b1 : b0;
        v4p0 = nck_eval(fmaf(w4a, pa, fmaf(w4b, pb, bb4)), cA, dA, cB, dB, cG);
    }
    {
        const float a0 = __shfl_sync(FULL, c[2], i4a);
        const float a1 = __shfl_sync(FULL, c[3], i4a);
        const float b0 = __shfl_sync(FULL, c[2], i4b);
        const float b1 = __shfl_sync(FULL, c[3], i4b);
        const float pa = hi ? a1 : a0;
        const float pb = hi ? b1 : b0;
        v4p1 = nck_eval(fmaf(w4a, pa, fmaf(w4b, pb, bb4)), cA, dA, cB, dB, cG);
    }

    // ---- level 5: N=8, all 4 elements in one warp-nck ----
    float v5;
    {
        const int k5 = lane & 7;
        const int half = (lane >> 3) & 1;
        const int s5a = half * 16 + (15 - 2 * k5);
        const int s5b = s5a - 1;
        const float w5a = sm[L5W + 2 * k5], w5b = sm[L5W + 2 * k5 + 1];
        const float bb5 = sm[L5B + k5];
        const float A0 = __shfl_sync(FULL, v4p0, s5a);
        const float A1 = __shfl_sync(FULL, v4p1, s5a);
        const float B0 = __shfl_sync(FULL, v4p0, s5b);
        const float B1 = __shfl_sync(FULL, v4p1, s5b);
        const float pa = hi ? A1 : A0;
        const float pb = hi ? B1 : B0;
        v5 = nck_eval(fmaf(w5a, pa, fmaf(w5b, pb, bb5)), cA, dA, cB, dB, cG);
    }

    // ---- level 6: N=4 (lane = 4e + k) ----
    float v6;
    {
        const int k6 = lane & 3;
        const int e6 = lane >> 2;
        const int s6 = (8 * e6 + 7 - 2 * k6) & 31;
        const float w6a = sm[L6W + 2 * k6], w6b = sm[L6W + 2 * k6 + 1];
        const float bb6 = sm[L6B + k6];
        const float pa = __shfl_sync(FULL, v5, s6);
        const float pb = __shfl_sync(FULL, v5, (s6 - 1) & 31);
        v6 = nck_eval(fmaf(w6a, pa, fmaf(w6b, pb, bb6)), cA, dA, cB, dB, cG);
    }

    // ---- level 7: N=2 (lane = 2e + k) ----
    float v7;
    {
        const int k7 = lane & 1;
        const int e7 = (lane >> 1) & 7;
        const int s7 = (4 * e7 + 3 - 2 * k7) & 31;
        const float w7a = sm[L7W + 2 * k7], w7b = sm[L7W + 2 * k7 + 1];
        const float bb7 = sm[L7B + k7];
        const float pa = __shfl_sync(FULL, v6, s7);
        const float pb = __shfl_sync(FULL, v6, (s7 - 1) & 31);
        v7 = nck_eval(fmaf(w7a, pa, fmaf(w7b, pb, bb7)), cA, dA, cB, dB, cG);
    }

    // ---- level 8: N=1 (lane = e) ----
    {
        const int e8 = lane & 3;
        const float pa = __shfl_sync(FULL, v7, (2 * e8 + 1) & 31);
        const float pb = __shfl_sync(FULL, v7, (2 * e8) & 31);
        const float v8 = nck_eval(fmaf(sm[L8W], pa, fmaf(sm[L8W + 1], pb, sm[L8B])),
                                  cA, dA, cB, dB, cG);
        if (lane < 4 && e0 + lane < B) {
            const float t = fmaf(v8, sm[SC + 3], sm[SC + 4]);
            out[e0 + lane] = rcpf(1.0f + ex2f(-t * L2E));
        }
    }
}

extern "C" void kernel_launch(void* const* d_in, const int* in_sizes, int n_in,
                              void* d_out, int out_size) {
    const float* x = (const float*)d_in[0];
    TreeParams P;
    if (in_sizes[2] == 511) {
        for (int l = 0; l < 9; ++l) {
            P.w[l] = (const float*)d_in[1 + 2 * l];
            P.b[l] = (const float*)d_in[2 + 2 * l];
        }
    } else {
        for (int l = 0; l < 9; ++l) {
            P.w[l] = (const float*)d_in[1 + l];
            P.b[l] = (const float*)d_in[10 + l];
        }
    }
    P.alpha  = (const float*)d_in[19];
    P.beta   = (const float*)d_in[20];
    P.gamma  = (const float*)d_in[21];
    P.root_w = (const float*)d_in[22];
    P.root_b = (const float*)d_in[23];

    const int B = in_sizes[0] / 256;              // 32768
    const int warps = (B + 3) / 4;                // 4 elements per warp
    const int grid = (warps + 7) / 8;             // 8 warps per 256-thread block
    asym_tree_kernel<<<grid, 256>>>(x, P, (float*)d_out, B);
}